// round 2
// baseline (speedup 1.0000x reference)
#include <cuda_runtime.h>

// Problem constants
// B=2, N=2048, C=1024, H=16, D=64, HALF=32

// ---------------- scratch (no allocations allowed) ----------------
__device__ float g_qkv[4096u * 3072u];     // [B*N, 3C]
__device__ float g_q[32u * 2048u * 64u];   // [B*H, N, D]
__device__ float g_k[32u * 2048u * 64u];
__device__ float g_v[32u * 2048u * 64u];
__device__ float g_ctx[4096u * 1024u];     // [B*N, C]

// ---------------- generic NT SGEMM: C[M,N] = A[M,K] @ B[N,K]^T (+bias) ----
// 128x128 block, K-tile 16, 256 threads, 8x8 microtile.
__global__ __launch_bounds__(256, 2)
void sgemm_nt(const float* __restrict__ A, const float* __restrict__ B,
              const float* __restrict__ bias, float* __restrict__ C,
              int M, int N, int K) {
    __shared__ float As[16][132];
    __shared__ float Bs[16][132];
    const int tid = threadIdx.x;
    const int bm = blockIdx.y * 128, bn = blockIdx.x * 128;
    const int ty = tid >> 4, tx = tid & 15;

    float acc[8][8];
#pragma unroll
    for (int i = 0; i < 8; i++)
#pragma unroll
        for (int j = 0; j < 8; j++) acc[i][j] = 0.f;

    for (int k0 = 0; k0 < K; k0 += 16) {
#pragma unroll
        for (int it = 0; it < 2; it++) {
            int idx = tid + it * 256;
            int row = idx >> 2;
            int c4  = (idx & 3) << 2;
            float4 a = *(const float4*)(A + (size_t)(bm + row) * K + k0 + c4);
            As[c4 + 0][row] = a.x; As[c4 + 1][row] = a.y;
            As[c4 + 2][row] = a.z; As[c4 + 3][row] = a.w;
            float4 b = *(const float4*)(B + (size_t)(bn + row) * K + k0 + c4);
            Bs[c4 + 0][row] = b.x; Bs[c4 + 1][row] = b.y;
            Bs[c4 + 2][row] = b.z; Bs[c4 + 3][row] = b.w;
        }
        __syncthreads();
#pragma unroll
        for (int kk = 0; kk < 16; kk++) {
            float ar[8], br[8];
            *(float4*)&ar[0] = *(const float4*)&As[kk][ty * 8];
            *(float4*)&ar[4] = *(const float4*)&As[kk][ty * 8 + 4];
            *(float4*)&br[0] = *(const float4*)&Bs[kk][tx * 8];
            *(float4*)&br[4] = *(const float4*)&Bs[kk][tx * 8 + 4];
#pragma unroll
            for (int i = 0; i < 8; i++)
#pragma unroll
                for (int j = 0; j < 8; j++)
                    acc[i][j] = fmaf(ar[i], br[j], acc[i][j]);
        }
        __syncthreads();
    }

#pragma unroll
    for (int i = 0; i < 8; i++) {
        size_t roff = (size_t)(bm + ty * 8 + i) * N + bn + tx * 8;
#pragma unroll
        for (int j4 = 0; j4 < 8; j4 += 4) {
            float4 r;
            r.x = acc[i][j4 + 0]; r.y = acc[i][j4 + 1];
            r.z = acc[i][j4 + 2]; r.w = acc[i][j4 + 3];
            if (bias) {
                r.x += bias[bn + tx * 8 + j4 + 0];
                r.y += bias[bn + tx * 8 + j4 + 1];
                r.z += bias[bn + tx * 8 + j4 + 2];
                r.w += bias[bn + tx * 8 + j4 + 3];
            }
            *(float4*)(C + roff + j4) = r;
        }
    }
}

// ---------------- RoPE + split into [B*H, N, D] ----------------
__global__ void rope_split_kernel(const float* __restrict__ qkv,
                                  const float* __restrict__ fcos,
                                  const float* __restrict__ fsin,
                                  float* __restrict__ q, float* __restrict__ k,
                                  float* __restrict__ v) {
    int idx = blockIdx.x * 256 + threadIdx.x;      // over B*N*H*HALF = 2^21
    int i = idx & 31;
    int h = (idx >> 5) & 15;
    int n = (idx >> 9) & 2047;
    int b = idx >> 20;
    const float* base = qkv + (size_t)(b * 2048 + n) * 3072 + h * 64 + 2 * i;
    float c = fcos[n * 32 + i], s = fsin[n * 32 + i];
    float2 qv = *(const float2*)(base);
    float2 kv = *(const float2*)(base + 1024);
    float2 vv = *(const float2*)(base + 2048);
    size_t o = ((size_t)((b * 16 + h) * 2048 + n)) * 64 + 2 * i;
    *(float2*)(q + o) = make_float2(qv.x * c - qv.y * s, qv.x * s + qv.y * c);
    *(float2*)(k + o) = make_float2(kv.x * c - kv.y * s, kv.x * s + kv.y * c);
    *(float2*)(v + o) = vv;
}

// ---------------- flash attention: 128 q-rows/block, 64-key tiles --------
// smem: Qst [64][132] transposed+scaled, Ks [64][65], Vs [64][64], Ps [128][64]
#define ATTN_SMEM ((64 * 132 + 64 * 65 + 64 * 64 + 128 * 64) * 4)

__global__ __launch_bounds__(256, 2)
void attn_kernel(const float* __restrict__ Q, const float* __restrict__ K,
                 const float* __restrict__ V, float* __restrict__ Out) {
    extern __shared__ float sm[];
    float* Qst = sm;                 // [d][row], row-stride 132
    float* Ks  = sm + 64 * 132;      // [krow][d], row-stride 65
    float* Vs  = Ks + 64 * 65;       // [krow][d], row-stride 64
    float* Ps  = Vs + 64 * 64;       // [qrow][k], row-stride 64

    const int tid = threadIdx.x;
    const int ty = tid >> 4, tx = tid & 15;
    const int ty8 = ty * 8, tx4 = tx * 4;
    const int bh = blockIdx.y;
    const int q0 = blockIdx.x * 128;

    // Load Q tile once: scale by 1/sqrt(D) and transpose into smem.
    const float* Qg = Q + ((size_t)bh * 2048 + q0) * 64;
#pragma unroll
    for (int it = 0; it < 8; it++) {
        int idx = tid + it * 256;
        int row = idx >> 4;
        int d4  = (idx & 15) << 2;
        float4 qv = *(const float4*)(Qg + row * 64 + d4);
        Qst[(d4 + 0) * 132 + row] = qv.x * 0.125f;
        Qst[(d4 + 1) * 132 + row] = qv.y * 0.125f;
        Qst[(d4 + 2) * 132 + row] = qv.z * 0.125f;
        Qst[(d4 + 3) * 132 + row] = qv.w * 0.125f;
    }

    float o[8][4];
    float mrow[8], lrow[8];
#pragma unroll
    for (int i = 0; i < 8; i++) {
        mrow[i] = -1e30f; lrow[i] = 0.f;
        o[i][0] = o[i][1] = o[i][2] = o[i][3] = 0.f;
    }

    const float* Kg0 = K + (size_t)bh * 2048 * 64;
    const float* Vg0 = V + (size_t)bh * 2048 * 64;

    for (int kt = 0; kt < 32; kt++) {
        const float* Kg = Kg0 + kt * 64 * 64;
        const float* Vg = Vg0 + kt * 64 * 64;
#pragma unroll
        for (int it = 0; it < 4; it++) {
            int idx = tid + it * 256;
            int row = idx >> 4;
            int d4  = (idx & 15) << 2;
            float4 kv = *(const float4*)(Kg + row * 64 + d4);
            Ks[row * 65 + d4 + 0] = kv.x;
            Ks[row * 65 + d4 + 1] = kv.y;
            Ks[row * 65 + d4 + 2] = kv.z;
            Ks[row * 65 + d4 + 3] = kv.w;
            *(float4*)(Vs + row * 64 + d4) = *(const float4*)(Vg + row * 64 + d4);
        }
        __syncthreads();

        // S = (Q*scale) @ K^T : thread owns rows ty8..+7, cols tx4..+3
        float s[8][4];
#pragma unroll
        for (int i = 0; i < 8; i++) s[i][0] = s[i][1] = s[i][2] = s[i][3] = 0.f;

#pragma unroll 8
        for (int d = 0; d < 64; d++) {
            float a[8];
            float4 t0 = *(const float4*)(Qst + d * 132 + ty8);
            float4 t1 = *(const float4*)(Qst + d * 132 + ty8 + 4);
            a[0] = t0.x; a[1] = t0.y; a[2] = t0.z; a[3] = t0.w;
            a[4] = t1.x; a[5] = t1.y; a[6] = t1.z; a[7] = t1.w;
            float kf0 = Ks[(tx4 + 0) * 65 + d];
            float kf1 = Ks[(tx4 + 1) * 65 + d];
            float kf2 = Ks[(tx4 + 2) * 65 + d];
            float kf3 = Ks[(tx4 + 3) * 65 + d];
#pragma unroll
            for (int i = 0; i < 8; i++) {
                s[i][0] = fmaf(a[i], kf0, s[i][0]);
                s[i][1] = fmaf(a[i], kf1, s[i][1]);
                s[i][2] = fmaf(a[i], kf2, s[i][2]);
                s[i][3] = fmaf(a[i], kf3, s[i][3]);
            }
        }

        // online softmax update (row reduce across tx = 16 lanes of half-warp)
#pragma unroll
        for (int i = 0; i < 8; i++) {
            float tm = fmaxf(fmaxf(s[i][0], s[i][1]), fmaxf(s[i][2], s[i][3]));
            tm = fmaxf(tm, __shfl_xor_sync(0xFFFFFFFFu, tm, 1, 16));
            tm = fmaxf(tm, __shfl_xor_sync(0xFFFFFFFFu, tm, 2, 16));
            tm = fmaxf(tm, __shfl_xor_sync(0xFFFFFFFFu, tm, 4, 16));
            tm = fmaxf(tm, __shfl_xor_sync(0xFFFFFFFFu, tm, 8, 16));
            float mnew  = fmaxf(mrow[i], tm);
            float alpha = __expf(mrow[i] - mnew);
            mrow[i] = mnew;
            float p0 = __expf(s[i][0] - mnew);
            float p1 = __expf(s[i][1] - mnew);
            float p2 = __expf(s[i][2] - mnew);
            float p3 = __expf(s[i][3] - mnew);
            float rs = (p0 + p1) + (p2 + p3);
            rs += __shfl_xor_sync(0xFFFFFFFFu, rs, 1, 16);
            rs += __shfl_xor_sync(0xFFFFFFFFu, rs, 2, 16);
            rs += __shfl_xor_sync(0xFFFFFFFFu, rs, 4, 16);
            rs += __shfl_xor_sync(0xFFFFFFFFu, rs, 8, 16);
            lrow[i] = lrow[i] * alpha + rs;
            o[i][0] *= alpha; o[i][1] *= alpha; o[i][2] *= alpha; o[i][3] *= alpha;
            *(float4*)(Ps + (ty8 + i) * 64 + tx4) = make_float4(p0, p1, p2, p3);
        }
        __syncthreads();

        // O += P @ V : thread owns rows ty8..+7, d-cols tx4..+3
#pragma unroll 4
        for (int k4 = 0; k4 < 16; k4++) {
            float4 v0 = *(const float4*)(Vs + (k4 * 4 + 0) * 64 + tx4);
            float4 v1 = *(const float4*)(Vs + (k4 * 4 + 1) * 64 + tx4);
            float4 v2 = *(const float4*)(Vs + (k4 * 4 + 2) * 64 + tx4);
            float4 v3 = *(const float4*)(Vs + (k4 * 4 + 3) * 64 + tx4);
#pragma unroll
            for (int i = 0; i < 8; i++) {
                float4 pv = *(const float4*)(Ps + (ty8 + i) * 64 + k4 * 4);
                o[i][0] = fmaf(pv.x, v0.x, fmaf(pv.y, v1.x, fmaf(pv.z, v2.x, fmaf(pv.w, v3.x, o[i][0]))));
                o[i][1] = fmaf(pv.x, v0.y, fmaf(pv.y, v1.y, fmaf(pv.z, v2.y, fmaf(pv.w, v3.y, o[i][1]))));
                o[i][2] = fmaf(pv.x, v0.z, fmaf(pv.y, v1.z, fmaf(pv.z, v2.z, fmaf(pv.w, v3.z, o[i][2]))));
                o[i][3] = fmaf(pv.x, v0.w, fmaf(pv.y, v1.w, fmaf(pv.z, v2.w, fmaf(pv.w, v3.w, o[i][3]))));
            }
        }
        __syncthreads();
    }

    // normalize + write to [B, N, C] context buffer
    const int b = bh >> 4, h = bh & 15;
#pragma unroll
    for (int i = 0; i < 8; i++) {
        float inv = 1.0f / lrow[i];
        float4 r = make_float4(o[i][0] * inv, o[i][1] * inv, o[i][2] * inv, o[i][3] * inv);
        *(float4*)(Out + ((size_t)(b * 2048 + q0 + ty8 + i)) * 1024 + h * 64 + tx4) = r;
    }
}

// ---------------- launch ----------------
extern "C" void kernel_launch(void* const* d_in, const int* in_sizes, int n_in,
                              void* d_out, int out_size) {
    const float* x      = (const float*)d_in[0];
    const float* qkv_w  = (const float*)d_in[1];
    const float* proj_w = (const float*)d_in[2];
    const float* proj_b = (const float*)d_in[3];
    const float* fcos   = (const float*)d_in[4];
    const float* fsin   = (const float*)d_in[5];
    float* out = (float*)d_out;

    float *qkv, *q, *k, *v, *ctx;
    cudaGetSymbolAddress((void**)&qkv, g_qkv);
    cudaGetSymbolAddress((void**)&q,   g_q);
    cudaGetSymbolAddress((void**)&k,   g_k);
    cudaGetSymbolAddress((void**)&v,   g_v);
    cudaGetSymbolAddress((void**)&ctx, g_ctx);

    // 1) QKV = x @ qkv_w^T   [4096,3072]
    sgemm_nt<<<dim3(3072 / 128, 4096 / 128), 256>>>(x, qkv_w, nullptr, qkv,
                                                    4096, 3072, 1024);
    // 2) RoPE + split into [B*H, N, D]
    rope_split_kernel<<<8192, 256>>>(qkv, fcos, fsin, q, k, v);
    // 3) fused attention -> ctx [B, N, C]
    cudaFuncSetAttribute(attn_kernel, cudaFuncAttributeMaxDynamicSharedMemorySize,
                         ATTN_SMEM);
    attn_kernel<<<dim3(2048 / 128, 32), 256, ATTN_SMEM>>>(q, k, v, ctx);
    // 4) out = ctx @ proj_w^T + proj_b   [4096,1024]
    sgemm_nt<<<dim3(1024 / 128, 4096 / 128), 256>>>(ctx, proj_w, proj_b, out,
                                                    4096, 1024, 1024);
}

// round 16
// speedup vs baseline: 2.1928x; 2.1928x over previous
#include <cuda_runtime.h>

// B=2, N=2048, C=1024, H=16, D=64, HALF=32

// ---------------- scratch ----------------
__device__ float g_qkv[4096u * 3072u];     // [B*N, 3C]
__device__ float g_q[32u * 2048u * 64u];   // [B*H, N, D]
__device__ float g_k[32u * 2048u * 64u];
__device__ float g_v[32u * 2048u * 64u];
__device__ float g_ctx[4096u * 1024u];     // [B*N, C]

// ---------------- tf32 helpers ----------------
__device__ __forceinline__ unsigned f2tf(float f) {
    unsigned u;
    asm("cvt.rna.tf32.f32 %0, %1;" : "=r"(u) : "f"(f));
    return u;
}

// D += A(16x8) * B(8x8), tf32 inputs, f32 accum. row.col.
__device__ __forceinline__ void mma8(float* d, const unsigned* a,
                                     unsigned b0, unsigned b1) {
    asm volatile(
        "mma.sync.aligned.m16n8k8.row.col.f32.tf32.tf32.f32 "
        "{%0,%1,%2,%3}, {%4,%5,%6,%7}, {%8,%9}, {%0,%1,%2,%3};"
        : "+f"(d[0]), "+f"(d[1]), "+f"(d[2]), "+f"(d[3])
        : "r"(a[0]), "r"(a[1]), "r"(a[2]), "r"(a[3]), "r"(b0), "r"(b1));
}

// ---------------- tf32 NT GEMM: C[M,N] = A[M,K] @ B[N,K]^T (+bias) -------
// 128x128 tile, BK=16, 256 threads, warps 2(m)x4(n), each warp 64x32.
__global__ __launch_bounds__(256, 2)
void gemm_tf32_nt(const float* __restrict__ A, const float* __restrict__ B,
                  const float* __restrict__ bias, float* __restrict__ C,
                  int M, int N, int K) {
    __shared__ unsigned As[128 * 20];
    __shared__ unsigned Bs[128 * 20];
    const int tid = threadIdx.x;
    const int lane = tid & 31, wid = tid >> 5;
    const int g = lane >> 2, tig = lane & 3;
    const int wm = (wid >> 2) * 64, wn = (wid & 3) * 32;
    const int bm = blockIdx.y * 128, bn = blockIdx.x * 128;
    const int lr = tid >> 2;            // 0..63
    const int lc = (tid & 3) << 2;      // 0,4,8,12

    const float* Ap = A + (size_t)(bm + lr) * K + lc;
    const float* Bp = B + (size_t)(bn + lr) * K + lc;

    float acc[4][4][4];
#pragma unroll
    for (int i = 0; i < 4; i++)
#pragma unroll
        for (int j = 0; j < 4; j++)
#pragma unroll
            for (int r = 0; r < 4; r++) acc[i][j][r] = 0.f;

    float4 pa0 = *(const float4*)(Ap);
    float4 pa1 = *(const float4*)(Ap + (size_t)64 * K);
    float4 pb0 = *(const float4*)(Bp);
    float4 pb1 = *(const float4*)(Bp + (size_t)64 * K);

    for (int k0 = 0; k0 < K; k0 += 16) {
        *(uint4*)(As + lr * 20 + lc) =
            make_uint4(f2tf(pa0.x), f2tf(pa0.y), f2tf(pa0.z), f2tf(pa0.w));
        *(uint4*)(As + (lr + 64) * 20 + lc) =
            make_uint4(f2tf(pa1.x), f2tf(pa1.y), f2tf(pa1.z), f2tf(pa1.w));
        *(uint4*)(Bs + lr * 20 + lc) =
            make_uint4(f2tf(pb0.x), f2tf(pb0.y), f2tf(pb0.z), f2tf(pb0.w));
        *(uint4*)(Bs + (lr + 64) * 20 + lc) =
            make_uint4(f2tf(pb1.x), f2tf(pb1.y), f2tf(pb1.z), f2tf(pb1.w));
        __syncthreads();

        if (k0 + 16 < K) {
            pa0 = *(const float4*)(Ap + k0 + 16);
            pa1 = *(const float4*)(Ap + (size_t)64 * K + k0 + 16);
            pb0 = *(const float4*)(Bp + k0 + 16);
            pb1 = *(const float4*)(Bp + (size_t)64 * K + k0 + 16);
        }

#pragma unroll
        for (int ks = 0; ks < 2; ks++) {
            unsigned a[4][4], b[4][2];
#pragma unroll
            for (int mt = 0; mt < 4; mt++) {
                int r0 = wm + mt * 16 + g;
                a[mt][0] = As[r0 * 20 + ks * 8 + tig];
                a[mt][1] = As[(r0 + 8) * 20 + ks * 8 + tig];
                a[mt][2] = As[r0 * 20 + ks * 8 + tig + 4];
                a[mt][3] = As[(r0 + 8) * 20 + ks * 8 + tig + 4];
            }
#pragma unroll
            for (int nt = 0; nt < 4; nt++) {
                int n0 = wn + nt * 8 + g;
                b[nt][0] = Bs[n0 * 20 + ks * 8 + tig];
                b[nt][1] = Bs[n0 * 20 + ks * 8 + tig + 4];
            }
#pragma unroll
            for (int mt = 0; mt < 4; mt++)
#pragma unroll
                for (int nt = 0; nt < 4; nt++)
                    mma8(acc[mt][nt], a[mt], b[nt][0], b[nt][1]);
        }
        __syncthreads();
    }

#pragma unroll
    for (int mt = 0; mt < 4; mt++) {
        int row = bm + wm + mt * 16 + g;
#pragma unroll
        for (int nt = 0; nt < 4; nt++) {
            int col = bn + wn + nt * 8 + 2 * tig;
            float b0v = bias ? bias[col] : 0.f;
            float b1v = bias ? bias[col + 1] : 0.f;
            *(float2*)(C + (size_t)row * N + col) =
                make_float2(acc[mt][nt][0] + b0v, acc[mt][nt][1] + b1v);
            *(float2*)(C + (size_t)(row + 8) * N + col) =
                make_float2(acc[mt][nt][2] + b0v, acc[mt][nt][3] + b1v);
        }
    }
}

// ---------------- RoPE + split into [B*H, N, D] ----------------
__global__ void rope_split_kernel(const float* __restrict__ qkv,
                                  const float* __restrict__ fcos,
                                  const float* __restrict__ fsin,
                                  float* __restrict__ q, float* __restrict__ k,
                                  float* __restrict__ v) {
    int idx = blockIdx.x * 256 + threadIdx.x;      // over B*N*H*HALF = 2^21
    int i = idx & 31;
    int h = (idx >> 5) & 15;
    int n = (idx >> 9) & 2047;
    int b = idx >> 20;
    const float* base = qkv + (size_t)(b * 2048 + n) * 3072 + h * 64 + 2 * i;
    float c = fcos[n * 32 + i], s = fsin[n * 32 + i];
    float2 qv = *(const float2*)(base);
    float2 kv = *(const float2*)(base + 1024);
    float2 vv = *(const float2*)(base + 2048);
    size_t o = ((size_t)((b * 16 + h) * 2048 + n)) * 64 + 2 * i;
    *(float2*)(q + o) = make_float2(qv.x * c - qv.y * s, qv.x * s + qv.y * c);
    *(float2*)(k + o) = make_float2(kv.x * c - kv.y * s, kv.x * s + kv.y * c);
    *(float2*)(v + o) = vv;
}

// ---------------- tf32 flash attention ----------------
// 128 q-rows/CTA, 64-key tiles, 8 warps, each warp owns 16 q-rows.
// smem word-stride 72 for all tiles (conflict-free for all fragment patterns).
#define AS 72
#define ATTN_SMEM ((128 * AS + 64 * AS + 64 * AS + 128 * AS) * 4)

__global__ __launch_bounds__(256, 1)
void attn_tf32(const float* __restrict__ Q, const float* __restrict__ K,
               const float* __restrict__ V, float* __restrict__ Out) {
    extern __shared__ unsigned smu[];
    unsigned* Qs = smu;                  // [128][72] tf32, pre-scaled
    unsigned* Ks = Qs + 128 * AS;        // [64][72]  tf32
    unsigned* Vs = Ks + 64 * AS;         // [64][72]  tf32
    unsigned* Ps = Vs + 64 * AS;         // [128][72] tf32

    const int tid = threadIdx.x, lane = tid & 31, wid = tid >> 5;
    const int g = lane >> 2, tig = lane & 3;
    const int bh = blockIdx.y, q0 = blockIdx.x * 128;
    const int r0 = wid * 16 + g;         // this thread's first q-row (local)

    // Q tile: load once, scale by 1/8, convert to tf32.
    const float* Qg = Q + ((size_t)bh * 2048 + q0) * 64;
#pragma unroll
    for (int it = 0; it < 8; it++) {
        int idx = tid + it * 256;
        int row = idx >> 4, c4 = (idx & 15) << 2;
        float4 qv = *(const float4*)(Qg + row * 64 + c4);
        *(uint4*)(Qs + row * AS + c4) =
            make_uint4(f2tf(qv.x * 0.125f), f2tf(qv.y * 0.125f),
                       f2tf(qv.z * 0.125f), f2tf(qv.w * 0.125f));
    }

    const float* Kg0 = K + (size_t)bh * 2048 * 64;
    const float* Vg0 = V + (size_t)bh * 2048 * 64;

    float m0 = -1e30f, m1 = -1e30f, l0 = 0.f, l1 = 0.f;
    float o[8][4];
#pragma unroll
    for (int nt = 0; nt < 8; nt++)
#pragma unroll
        for (int r = 0; r < 4; r++) o[nt][r] = 0.f;

    // prefetch first K/V tile
    float4 kr[4], vr[4];
#pragma unroll
    for (int it = 0; it < 4; it++) {
        int idx = tid + it * 256;
        int row = idx >> 4, c4 = (idx & 15) << 2;
        kr[it] = *(const float4*)(Kg0 + row * 64 + c4);
        vr[it] = *(const float4*)(Vg0 + row * 64 + c4);
    }

    for (int kt = 0; kt < 32; kt++) {
        __syncthreads();   // prev iteration's reads of Ks/Vs complete
#pragma unroll
        for (int it = 0; it < 4; it++) {
            int idx = tid + it * 256;
            int row = idx >> 4, c4 = (idx & 15) << 2;
            *(uint4*)(Ks + row * AS + c4) =
                make_uint4(f2tf(kr[it].x), f2tf(kr[it].y),
                           f2tf(kr[it].z), f2tf(kr[it].w));
            *(uint4*)(Vs + row * AS + c4) =
                make_uint4(f2tf(vr[it].x), f2tf(vr[it].y),
                           f2tf(vr[it].z), f2tf(vr[it].w));
        }
        __syncthreads();

        if (kt < 31) {
            const float* Kg = Kg0 + (size_t)(kt + 1) * 64 * 64;
            const float* Vg = Vg0 + (size_t)(kt + 1) * 64 * 64;
#pragma unroll
            for (int it = 0; it < 4; it++) {
                int idx = tid + it * 256;
                int row = idx >> 4, c4 = (idx & 15) << 2;
                kr[it] = *(const float4*)(Kg + row * 64 + c4);
                vr[it] = *(const float4*)(Vg + row * 64 + c4);
            }
        }

        // ---- S = (Q/8) @ K^T  (128x64, this warp: rows r0-block) ----
        float s[8][4];
#pragma unroll
        for (int nt = 0; nt < 8; nt++)
#pragma unroll
            for (int r = 0; r < 4; r++) s[nt][r] = 0.f;

#pragma unroll
        for (int ks = 0; ks < 8; ks++) {
            unsigned a[4];
            a[0] = Qs[r0 * AS + ks * 8 + tig];
            a[1] = Qs[(r0 + 8) * AS + ks * 8 + tig];
            a[2] = Qs[r0 * AS + ks * 8 + tig + 4];
            a[3] = Qs[(r0 + 8) * AS + ks * 8 + tig + 4];
#pragma unroll
            for (int nt = 0; nt < 8; nt++) {
                unsigned b0 = Ks[(nt * 8 + g) * AS + ks * 8 + tig];
                unsigned b1 = Ks[(nt * 8 + g) * AS + ks * 8 + tig + 4];
                mma8(s[nt], a, b0, b1);
            }
        }

        // ---- online softmax (rows r0 and r0+8; quad = lanes sharing a row) --
        float tm0 = -1e30f, tm1 = -1e30f;
#pragma unroll
        for (int nt = 0; nt < 8; nt++) {
            tm0 = fmaxf(tm0, fmaxf(s[nt][0], s[nt][1]));
            tm1 = fmaxf(tm1, fmaxf(s[nt][2], s[nt][3]));
        }
        tm0 = fmaxf(tm0, __shfl_xor_sync(0xFFFFFFFFu, tm0, 1));
        tm0 = fmaxf(tm0, __shfl_xor_sync(0xFFFFFFFFu, tm0, 2));
        tm1 = fmaxf(tm1, __shfl_xor_sync(0xFFFFFFFFu, tm1, 1));
        tm1 = fmaxf(tm1, __shfl_xor_sync(0xFFFFFFFFu, tm1, 2));
        float mn0 = fmaxf(m0, tm0), mn1 = fmaxf(m1, tm1);
        float al0 = __expf(m0 - mn0), al1 = __expf(m1 - mn1);
        m0 = mn0; m1 = mn1;
        float rs0 = 0.f, rs1 = 0.f;
#pragma unroll
        for (int nt = 0; nt < 8; nt++) {
            float p0 = __expf(s[nt][0] - mn0);
            float p1 = __expf(s[nt][1] - mn0);
            float p2 = __expf(s[nt][2] - mn1);
            float p3 = __expf(s[nt][3] - mn1);
            rs0 += p0 + p1; rs1 += p2 + p3;
            Ps[r0 * AS + nt * 8 + 2 * tig]       = f2tf(p0);
            Ps[r0 * AS + nt * 8 + 2 * tig + 1]   = f2tf(p1);
            Ps[(r0 + 8) * AS + nt * 8 + 2 * tig]     = f2tf(p2);
            Ps[(r0 + 8) * AS + nt * 8 + 2 * tig + 1] = f2tf(p3);
        }
        rs0 += __shfl_xor_sync(0xFFFFFFFFu, rs0, 1);
        rs0 += __shfl_xor_sync(0xFFFFFFFFu, rs0, 2);
        rs1 += __shfl_xor_sync(0xFFFFFFFFu, rs1, 1);
        rs1 += __shfl_xor_sync(0xFFFFFFFFu, rs1, 2);
        l0 = l0 * al0 + rs0;
        l1 = l1 * al1 + rs1;
#pragma unroll
        for (int nt = 0; nt < 8; nt++) {
            o[nt][0] *= al0; o[nt][1] *= al0;
            o[nt][2] *= al1; o[nt][3] *= al1;
        }
        __syncwarp();   // Ps rows are private to this warp; order STS->LDS

        // ---- O += P @ V ----
#pragma unroll
        for (int ks = 0; ks < 8; ks++) {
            unsigned a[4];
            a[0] = Ps[r0 * AS + ks * 8 + tig];
            a[1] = Ps[(r0 + 8) * AS + ks * 8 + tig];
            a[2] = Ps[r0 * AS + ks * 8 + tig + 4];
            a[3] = Ps[(r0 + 8) * AS + ks * 8 + tig + 4];
#pragma unroll
            for (int nt = 0; nt < 8; nt++) {
                unsigned b0 = Vs[(ks * 8 + tig) * AS + nt * 8 + g];
                unsigned b1 = Vs[(ks * 8 + tig + 4) * AS + nt * 8 + g];
                mma8(o[nt], a, b0, b1);
            }
        }
    }

    // ---- normalize + write [B, N, C] ----
    const int b = bh >> 4, h = bh & 15;
    float i0 = 1.f / l0, i1 = 1.f / l1;
    int rg = q0 + r0;
#pragma unroll
    for (int nt = 0; nt < 8; nt++) {
        int col = h * 64 + nt * 8 + 2 * tig;
        *(float2*)(Out + (size_t)(b * 2048 + rg) * 1024 + col) =
            make_float2(o[nt][0] * i0, o[nt][1] * i0);
        *(float2*)(Out + (size_t)(b * 2048 + rg + 8) * 1024 + col) =
            make_float2(o[nt][2] * i1, o[nt][3] * i1);
    }
}

// ---------------- launch ----------------
extern "C" void kernel_launch(void* const* d_in, const int* in_sizes, int n_in,
                              void* d_out, int out_size) {
    const float* x      = (const float*)d_in[0];
    const float* qkv_w  = (const float*)d_in[1];
    const float* proj_w = (const float*)d_in[2];
    const float* proj_b = (const float*)d_in[3];
    const float* fcos   = (const float*)d_in[4];
    const float* fsin   = (const float*)d_in[5];
    float* out = (float*)d_out;

    float *qkv, *q, *k, *v, *ctx;
    cudaGetSymbolAddress((void**)&qkv, g_qkv);
    cudaGetSymbolAddress((void**)&q,   g_q);
    cudaGetSymbolAddress((void**)&k,   g_k);
    cudaGetSymbolAddress((void**)&v,   g_v);
    cudaGetSymbolAddress((void**)&ctx, g_ctx);

    // 1) QKV = x @ qkv_w^T   [4096,3072]
    gemm_tf32_nt<<<dim3(3072 / 128, 4096 / 128), 256>>>(x, qkv_w, nullptr, qkv,
                                                        4096, 3072, 1024);
    // 2) RoPE + split into [B*H, N, D]
    rope_split_kernel<<<8192, 256>>>(qkv, fcos, fsin, q, k, v);
    // 3) fused attention -> ctx [B, N, C]
    cudaFuncSetAttribute(attn_tf32, cudaFuncAttributeMaxDynamicSharedMemorySize,
                         ATTN_SMEM);
    attn_tf32<<<dim3(2048 / 128, 32), 256, ATTN_SMEM>>>(q, k, v, ctx);
    // 4) out = ctx @ proj_w^T + proj_b   [4096,1024]
    gemm_tf32_nt<<<dim3(1024 / 128, 4096 / 128), 256>>>(ctx, proj_w, proj_b, out,
                                                        4096, 1024, 1024);
}